// round 1
// baseline (speedup 1.0000x reference)
#include <cuda_runtime.h>
#include <math_constants.h>

// RandomFeatures: dilated 11-tap conv over T positions per (b,k), then
// masked max + positive-proportion reduction.
//
// Inputs (metadata order):
//   0: x        float32 [B*T]
//   1: weight   float32 [K*11]   (taps beyond klen are exactly 0)
//   2: bias     float32 [K]
//   3: dilation int32   [K]
//   4: padding  int32   [K]
//   5: out_len  int32   [K]
// Output: float32 [B, 2K]  (out[b,2k]=max, out[b,2k+1]=ppv)

#define MAX_KLEN 11
#define PADW 256          // zero-pad halo on each side of x in shared
#define WARPS_PER_CTA 8

__global__ void rf_kernel(const float* __restrict__ x,
                          const float* __restrict__ w,
                          const float* __restrict__ bias,
                          const int*   __restrict__ dil,
                          const int*   __restrict__ padr,
                          const int*   __restrict__ olen,
                          float* __restrict__ out,
                          int B, int T, int K) {
    extern __shared__ float xs[];   // size T + 2*PADW floats, zero-padded halo

    const int b    = blockIdx.y;
    const int lane = threadIdx.x & 31;
    const int warp = threadIdx.x >> 5;
    const int k    = blockIdx.x * WARPS_PER_CTA + warp;

    // Cooperative load of x[b,:] with zeroed halo.
    const int total = T + 2 * PADW;
    for (int i = threadIdx.x; i < total; i += blockDim.x) {
        int t = i - PADW;
        xs[i] = (t >= 0 && t < T) ? x[(size_t)b * T + t] : 0.0f;
    }
    __syncthreads();

    if (k >= K) return;

    // Per-k parameters (uniform across warp -> broadcast loads).
    const int   d  = dil[k];
    const int   pd = padr[k];
    const int   ol = olen[k];
    const float bs = bias[k];

    float wreg[MAX_KLEN];
#pragma unroll
    for (int j = 0; j < MAX_KLEN; j++) wreg[j] = __ldg(&w[(size_t)k * MAX_KLEN + j]);

    // Pointer so that xp[p + j*d] == x_padded value at index p - pd + j*d.
    const float* xp = xs + (PADW - pd);

    float mx  = -CUDART_INF_F;
    float cnt = 0.0f;

    // Main loop: 4 positions per thread per iteration (ILP).
    int p0 = lane;
    for (; p0 + 96 < T; p0 += 128) {
        float a0 = bs, a1 = bs, a2 = bs, a3 = bs;
#pragma unroll
        for (int j = 0; j < MAX_KLEN; j++) {
            const float wj = wreg[j];
            const int   o  = p0 + j * d;
            a0 = fmaf(wj, xp[o],      a0);
            a1 = fmaf(wj, xp[o + 32], a1);
            a2 = fmaf(wj, xp[o + 64], a2);
            a3 = fmaf(wj, xp[o + 96], a3);
        }
        if (p0      < ol) { mx = fmaxf(mx, a0); cnt += (a0 > 0.0f) ? 1.0f : 0.0f; }
        if (p0 + 32 < ol) { mx = fmaxf(mx, a1); cnt += (a1 > 0.0f) ? 1.0f : 0.0f; }
        if (p0 + 64 < ol) { mx = fmaxf(mx, a2); cnt += (a2 > 0.0f) ? 1.0f : 0.0f; }
        if (p0 + 96 < ol) { mx = fmaxf(mx, a3); cnt += (a3 > 0.0f) ? 1.0f : 0.0f; }
    }
    // Remainder (not taken when T % 128 == 0).
    for (; p0 < T; p0 += 32) {
        float a0 = bs;
#pragma unroll
        for (int j = 0; j < MAX_KLEN; j++)
            a0 = fmaf(wreg[j], xp[p0 + j * d], a0);
        if (p0 < ol) { mx = fmaxf(mx, a0); cnt += (a0 > 0.0f) ? 1.0f : 0.0f; }
    }

    // Warp reduction over positions.
#pragma unroll
    for (int off = 16; off > 0; off >>= 1) {
        mx   = fmaxf(mx, __shfl_xor_sync(0xFFFFFFFFu, mx, off));
        cnt +=            __shfl_xor_sync(0xFFFFFFFFu, cnt, off);
    }

    if (lane == 0) {
        float* o = out + (size_t)b * 2 * K + 2 * k;
        o[0] = mx;
        o[1] = cnt / (float)ol;
    }
}

extern "C" void kernel_launch(void* const* d_in, const int* in_sizes, int n_in,
                              void* d_out, int out_size) {
    const float* x    = (const float*)d_in[0];
    const float* w    = (const float*)d_in[1];
    const float* bias = (const float*)d_in[2];
    const int*   dil  = (const int*)d_in[3];
    const int*   padr = (const int*)d_in[4];
    const int*   olen = (const int*)d_in[5];
    float* out = (float*)d_out;

    const int K = in_sizes[2];                 // bias element count
    const int B = out_size / (2 * K);
    const int T = in_sizes[0] / B;

    dim3 block(32 * WARPS_PER_CTA);
    dim3 grid((K + WARPS_PER_CTA - 1) / WARPS_PER_CTA, B);
    size_t smem = (size_t)(T + 2 * PADW) * sizeof(float);

    rf_kernel<<<grid, block, smem>>>(x, w, bias, dil, padr, olen, out, B, T, K);
}